// round 1
// baseline (speedup 1.0000x reference)
#include <cuda_runtime.h>

#define EPS 1e-5f

typedef unsigned long long ull;

// ---------------- scratch (static device memory; no allocations) ----------------
static __device__ __align__(16) float g_x2[128 * 64 * 3136];       // 102.8 MB: x * attn
static __device__ __align__(16) float g_gate[2 * 16 * 8 * 3136];   // 3.2 MB : tanh(conv3d)
static __device__ float g_psum[64 * 512];                          // BN partial sums
static __device__ float g_psq[64 * 512];                           // BN partial sumsq
static __device__ float g_scale[64];
static __device__ float g_bias[64];

// ---------------- f32x2 helpers ----------------
__device__ __forceinline__ ull pack2(float a, float b) {
    ull r;
    asm("mov.b64 %0, {%1, %2};" : "=l"(r) : "r"(__float_as_uint(a)), "r"(__float_as_uint(b)));
    return r;
}
__device__ __forceinline__ void unpack2(ull v, float& a, float& b) {
    unsigned int ua, ub;
    asm("mov.b64 {%0, %1}, %2;" : "=r"(ua), "=r"(ub) : "l"(v));
    a = __uint_as_float(ua);
    b = __uint_as_float(ub);
}
__device__ __forceinline__ ull fma2(ull a, ull b, ull c) {
    ull d;
    asm("fma.rn.f32x2 %0, %1, %2, %3;" : "=l"(d) : "l"(a), "l"(b), "l"(c));
    return d;
}

// =====================================================================
// Kernel A: attn conv2d (4 heads, 3x3, C=64 in) -> sigmoid(relu(.)),
//           x2 = x * attn broadcast, BN partial sums.
// grid (128, 4), block 224. Tile: 14 rows x 56 cols per block.
// Threads 0..195 each compute a 2h x 2w pixel patch; heads packed in f32x2.
// =====================================================================
__global__ void __launch_bounds__(224) kernelA(const float* __restrict__ x,
                                               const float* __restrict__ attn_w,
                                               const float* __restrict__ attn_b) {
    __shared__ ull s_w[64][9][2];                       // {h0,h1},{h2,h3} packed weights
    __shared__ __align__(16) float s_tile[4][16][58];   // 4 ch x (14+2) rows x (56+2) cols
    __shared__ __align__(16) float s_attn[4][14 * 56];  // attn outputs for this tile

    const int n = blockIdx.x;
    const int h_base = blockIdx.y * 14;
    const int tid = threadIdx.x;

    // pack attention weights: attn_w is (4, 64, 3, 3)
    for (int i = tid; i < 64 * 9; i += 224) {
        int c = i / 9, k = i - c * 9;
        s_w[c][k][0] = pack2(attn_w[c * 9 + k], attn_w[576 + c * 9 + k]);
        s_w[c][k][1] = pack2(attn_w[1152 + c * 9 + k], attn_w[1728 + c * 9 + k]);
    }

    const bool active = tid < 196;
    const int wi = tid % 28, hi = tid / 28;
    const int w0p = 2 * wi, h0p = 2 * hi;  // pixel patch origin within tile

    ull acc[2][2][2];  // [oh][ow][head-pair]
#pragma unroll
    for (int a1 = 0; a1 < 2; a1++)
#pragma unroll
        for (int a2 = 0; a2 < 2; a2++)
#pragma unroll
            for (int a3 = 0; a3 < 2; a3++) acc[a1][a2][a3] = 0ull;

    const float* xn = x + n * 64 * 3136;

    for (int c0 = 0; c0 < 64; c0 += 4) {
        __syncthreads();
        // load 4-channel tile with zero halo
        for (int i = tid; i < 4 * 16 * 58; i += 224) {
            int cc = i / (16 * 58);
            int rem = i - cc * (16 * 58);
            int r = rem / 58, col = rem - r * 58;
            int gh = h_base - 1 + r, gw = col - 1;
            float v = 0.f;
            if ((unsigned)gh < 56u && (unsigned)gw < 56u)
                v = xn[(c0 + cc) * 3136 + gh * 56 + gw];
            s_tile[cc][r][col] = v;
        }
        __syncthreads();
        if (active) {
#pragma unroll
            for (int cc = 0; cc < 4; cc++) {
                ull wv[9][2];
#pragma unroll
                for (int k = 0; k < 9; k++) {
                    wv[k][0] = s_w[c0 + cc][k][0];
                    wv[k][1] = s_w[c0 + cc][k][1];
                }
#pragma unroll
                for (int r = 0; r < 4; r++) {
                    ull a = *(const ull*)&s_tile[cc][h0p + r][w0p];
                    ull b = *(const ull*)&s_tile[cc][h0p + r][w0p + 2];
                    float v0, v1, v2, v3;
                    unpack2(a, v0, v1);
                    unpack2(b, v2, v3);
                    ull p[4] = {pack2(v0, v0), pack2(v1, v1), pack2(v2, v2), pack2(v3, v3)};
#pragma unroll
                    for (int oh = 0; oh < 2; oh++) {
                        int dh = r - oh;
                        if (dh < 0 || dh > 2) continue;
#pragma unroll
                        for (int dw = 0; dw < 3; dw++) {
                            ull wl = wv[dh * 3 + dw][0];
                            ull wh = wv[dh * 3 + dw][1];
                            acc[oh][0][0] = fma2(p[dw], wl, acc[oh][0][0]);
                            acc[oh][0][1] = fma2(p[dw], wh, acc[oh][0][1]);
                            acc[oh][1][0] = fma2(p[dw + 1], wl, acc[oh][1][0]);
                            acc[oh][1][1] = fma2(p[dw + 1], wh, acc[oh][1][1]);
                        }
                    }
                }
            }
        }
    }
    __syncthreads();
    if (active) {
        float b0 = attn_b[0], b1 = attn_b[1], b2 = attn_b[2], b3 = attn_b[3];
#pragma unroll
        for (int oh = 0; oh < 2; oh++)
#pragma unroll
            for (int ow = 0; ow < 2; ow++) {
                float a0, a1, a2, a3;
                unpack2(acc[oh][ow][0], a0, a1);
                unpack2(acc[oh][ow][1], a2, a3);
                a0 = fmaxf(a0 + b0, 0.f);
                a1 = fmaxf(a1 + b1, 0.f);
                a2 = fmaxf(a2 + b2, 0.f);
                a3 = fmaxf(a3 + b3, 0.f);
                int px = (h0p + oh) * 56 + w0p + ow;
                s_attn[0][px] = 1.f / (1.f + __expf(-a0));
                s_attn[1][px] = 1.f / (1.f + __expf(-a1));
                s_attn[2][px] = 1.f / (1.f + __expf(-a2));
                s_attn[3][px] = 1.f / (1.f + __expf(-a3));
            }
    }
    __syncthreads();

    // phase 2: x2 = x * attn, BN partial sums (deterministic slots)
    const int warp = tid >> 5, lane = tid & 31;
    const int pidx = n * 4 + blockIdx.y;  // 0..511
    for (int c = warp; c < 64; c += 7) {
        int head = c >> 4;
        const float4* xp = (const float4*)(xn + c * 3136 + h_base * 56);
        float4* x2p = (float4*)(g_x2 + n * 64 * 3136 + c * 3136 + h_base * 56);
        const float4* ap = (const float4*)&s_attn[head][0];
        float sum = 0.f, sq = 0.f;
        for (int i = lane; i < 196; i += 32) {
            float4 xv = xp[i], av = ap[i];
            float4 v;
            v.x = xv.x * av.x;
            v.y = xv.y * av.y;
            v.z = xv.z * av.z;
            v.w = xv.w * av.w;
            x2p[i] = v;
            sum += (v.x + v.y) + (v.z + v.w);
            sq += (v.x * v.x + v.y * v.y) + (v.z * v.z + v.w * v.w);
        }
#pragma unroll
        for (int o = 16; o; o >>= 1) {
            sum += __shfl_down_sync(0xffffffffu, sum, o);
            sq += __shfl_down_sync(0xffffffffu, sq, o);
        }
        if (lane == 0) {
            g_psum[c * 512 + pidx] = sum;
            g_psq[c * 512 + pidx] = sq;
        }
    }
}

// =====================================================================
// Kernel B: reduce BN partials -> per-channel scale/bias. grid 64, block 32.
// =====================================================================
__global__ void kernelB(const float* __restrict__ gamma, const float* __restrict__ beta) {
    int c = blockIdx.x, lane = threadIdx.x;
    float s = 0.f, q = 0.f;
    for (int i = lane; i < 512; i += 32) {
        s += g_psum[c * 512 + i];
        q += g_psq[c * 512 + i];
    }
#pragma unroll
    for (int o = 16; o; o >>= 1) {
        s += __shfl_down_sync(0xffffffffu, s, o);
        q += __shfl_down_sync(0xffffffffu, q, o);
    }
    if (lane == 0) {
        const float inv_n = 1.f / 401408.f;  // B*T*H*W
        float mean = s * inv_n;
        float var = q * inv_n - mean * mean;
        float sc = gamma[c] * rsqrtf(var + EPS);
        g_scale[c] = sc;
        g_bias[c] = beta[c] - mean * sc;
    }
}

// =====================================================================
// Kernel C: grouped conv3d (3x3x3, 32 in -> 1 out per group) on relu(bn(x2)),
//           tanh -> g_gate. grid (128 bt, 2 g, 2 htile), block 224.
// Threads 0..195 each compute 4h x 2w outputs (f32x2 over the w pair).
// =====================================================================
__global__ void __launch_bounds__(224) kernelC(const float* __restrict__ w3,
                                               const float* __restrict__ b3) {
    __shared__ ull s_w3[32][27];                        // {w,w} packed weights
    __shared__ __align__(16) float s_tile[4][30][58];   // 4 ch x (28+2) rows x 58 cols

    const int bt = blockIdx.x;  // b*8 + t
    const int b = bt >> 3, t = bt & 7;
    const int g = blockIdx.y;
    const int h_off = blockIdx.z * 28;
    const int tid = threadIdx.x;

    for (int i = tid; i < 32 * 27; i += 224) {
        float w = w3[g * 864 + i];
        s_w3[i / 27][i % 27] = pack2(w, w);
    }

    const bool active = tid < 196;
    const int wi = tid % 28, hi = tid / 28;
    const int w0p = 2 * wi, h0p = 4 * hi;

    ull acc[4];
#pragma unroll
    for (int i = 0; i < 4; i++) acc[i] = 0ull;

    for (int dt = 0; dt < 3; dt++) {
        int ts = t + dt - 1;
        if ((unsigned)ts >= 8u) continue;  // temporal zero-pad (block-uniform)
        const float* xsrc = g_x2 + (b * 8 + ts) * 64 * 3136;
        for (int c0 = 0; c0 < 32; c0 += 4) {
            __syncthreads();
            for (int i = tid; i < 4 * 30 * 58; i += 224) {
                int cc = i / (30 * 58);
                int rem = i - cc * (30 * 58);
                int r = rem / 58, col = rem - r * 58;
                int gh = h_off - 1 + r, gw = col - 1;
                int c = g * 32 + c0 + cc;
                float v = 0.f;
                if ((unsigned)gh < 56u && (unsigned)gw < 56u) {
                    v = xsrc[c * 3136 + gh * 56 + gw];
                    v = fmaxf(v * g_scale[c] + g_bias[c], 0.f);  // relu(bn(.))
                }
                s_tile[cc][r][col] = v;
            }
            __syncthreads();
            if (active) {
#pragma unroll
                for (int cc = 0; cc < 4; cc++) {
                    ull wv[9];
#pragma unroll
                    for (int k = 0; k < 9; k++) wv[k] = s_w3[c0 + cc][dt * 9 + k];
#pragma unroll
                    for (int r = 0; r < 6; r++) {
                        ull a = *(const ull*)&s_tile[cc][h0p + r][w0p];
                        ull bb = *(const ull*)&s_tile[cc][h0p + r][w0p + 2];
                        float v0, v1, v2, v3;
                        unpack2(a, v0, v1);
                        unpack2(bb, v2, v3);
                        ull pr[3];
                        pr[0] = a;
                        pr[1] = pack2(v1, v2);
                        pr[2] = bb;
#pragma unroll
                        for (int oh = 0; oh < 4; oh++) {
                            int dh = r - oh;
                            if (dh < 0 || dh > 2) continue;
#pragma unroll
                            for (int dw = 0; dw < 3; dw++)
                                acc[oh] = fma2(pr[dw], wv[dh * 3 + dw], acc[oh]);
                        }
                    }
                }
            }
        }
    }
    if (active) {
        float cb = b3[g];
        float* gp = g_gate + ((g * 16 + b) * 8 + t) * 3136;
#pragma unroll
        for (int oh = 0; oh < 4; oh++) {
            float r0, r1;
            unpack2(acc[oh], r0, r1);
            int h = h_off + h0p + oh;
            gp[h * 56 + w0p] = tanhf(r0 + cb);
            gp[h * 56 + w0p + 1] = tanhf(r1 + cb);
        }
    }
}

// =====================================================================
// Kernel D: gate apply + temporal shift + channel interleave, float4 streaming.
// grid 3136, block 256. One thread = (b, c_out, h, 4w), loops all T=8.
// =====================================================================
__global__ void __launch_bounds__(256) kernelD(float* __restrict__ out) {
    int idx = blockIdx.x * 256 + threadIdx.x;  // 0..802815
    int w4 = idx % 14;
    int tmp = idx / 14;
    int h = tmp % 56;
    tmp /= 56;
    int c_out = tmp & 63;
    int b = tmp >> 6;

    int gsel = c_out >> 5;
    int cc = c_out & 31;
    int c_src = gsel * 32 + (cc & 1) * 16 + (cc >> 1);  // de-interleave

    int hw = h * 56 + w4 * 4;
    const float4* gbase = (const float4*)(g_gate + ((gsel * 16 + b) * 8) * 3136 + hw);
    int xoff0 = (b * 8) * 64 * 3136 + c_src * 3136 + hw;
    int ooff0 = (b * 8) * 64 * 3136 + c_out * 3136 + hw;

    float4 py = make_float4(0.f, 0.f, 0.f, 0.f);  // gate*x carried from prior t
    if (gsel == 0) {
        // out[t] = g[t+1]*x[t+1] + (1-g[t])*x[t]   (t = T-1 gets no shifted term)
#pragma unroll
        for (int t = 7; t >= 0; --t) {
            float4 xt = *(const float4*)(g_x2 + xoff0 + t * 64 * 3136);
            float4 gt = gbase[t * 784];
            float4 o;
            o.x = py.x + (1.f - gt.x) * xt.x;
            o.y = py.y + (1.f - gt.y) * xt.y;
            o.z = py.z + (1.f - gt.z) * xt.z;
            o.w = py.w + (1.f - gt.w) * xt.w;
            *(float4*)(out + ooff0 + t * 64 * 3136) = o;
            py.x = gt.x * xt.x;
            py.y = gt.y * xt.y;
            py.z = gt.z * xt.z;
            py.w = gt.w * xt.w;
        }
    } else {
        // out[t] = g[t-1]*x[t-1] + (1-g[t])*x[t]   (t = 0 gets no shifted term)
#pragma unroll
        for (int t = 0; t < 8; ++t) {
            float4 xt = *(const float4*)(g_x2 + xoff0 + t * 64 * 3136);
            float4 gt = gbase[t * 784];
            float4 o;
            o.x = py.x + (1.f - gt.x) * xt.x;
            o.y = py.y + (1.f - gt.y) * xt.y;
            o.z = py.z + (1.f - gt.z) * xt.z;
            o.w = py.w + (1.f - gt.w) * xt.w;
            *(float4*)(out + ooff0 + t * 64 * 3136) = o;
            py.x = gt.x * xt.x;
            py.y = gt.y * xt.y;
            py.z = gt.z * xt.z;
            py.w = gt.w * xt.w;
        }
    }
}

// =====================================================================
extern "C" void kernel_launch(void* const* d_in, const int* in_sizes, int n_in,
                              void* d_out, int out_size) {
    const float* x = (const float*)d_in[0];
    const float* attn_w = (const float*)d_in[1];
    const float* attn_b = (const float*)d_in[2];
    const float* gamma = (const float*)d_in[3];
    const float* beta = (const float*)d_in[4];
    const float* w3 = (const float*)d_in[5];
    const float* b3 = (const float*)d_in[6];
    float* out = (float*)d_out;

    kernelA<<<dim3(128, 4), 224>>>(x, attn_w, attn_b);
    kernelB<<<64, 32>>>(gamma, beta);
    kernelC<<<dim3(128, 2, 2), 224>>>(w3, b3);
    kernelD<<<3136, 256>>>(out);
}

// round 2
// speedup vs baseline: 1.4353x; 1.4353x over previous
#include <cuda_runtime.h>

#define EPS 1e-5f

typedef unsigned long long ull;

// ---------------- scratch (static device memory; no allocations) ----------------
static __device__ __align__(16) float g_x2[128 * 64 * 3136];       // 102.8 MB: x * attn
static __device__ __align__(16) float g_gate[2 * 16 * 8 * 3136];   // 3.2 MB : tanh(conv3d)
static __device__ float g_psum[64 * 512];                          // BN partial sums
static __device__ float g_psq[64 * 512];                           // BN partial sumsq
static __device__ float g_scale[64];
static __device__ float g_bias[64];

// ---------------- f32x2 helpers ----------------
__device__ __forceinline__ ull pack2(float a, float b) {
    ull r;
    asm("mov.b64 %0, {%1, %2};" : "=l"(r) : "r"(__float_as_uint(a)), "r"(__float_as_uint(b)));
    return r;
}
__device__ __forceinline__ void unpack2(ull v, float& a, float& b) {
    unsigned int ua, ub;
    asm("mov.b64 {%0, %1}, %2;" : "=r"(ua), "=r"(ub) : "l"(v));
    a = __uint_as_float(ua);
    b = __uint_as_float(ub);
}
__device__ __forceinline__ ull fma2(ull a, ull b, ull c) {
    ull d;
    asm("fma.rn.f32x2 %0, %1, %2, %3;" : "=l"(d) : "l"(a), "l"(b), "l"(c));
    return d;
}

// meta layout: bits[0:12) smem offset, [12:26) gmem offset, [26:28) cc, [28] valid
#define NLOAD 17  // ceil(3712 / 224)

// =====================================================================
// Kernel A: attn conv2d (4 heads, 3x3, C=64) -> sigmoid(relu(.)),
//           x2 = x * attn, BN partial sums.
// grid (128, 4), block 224. Tile 14h x 56w. Thread (of 196) = 1h x 4w,
// 4 heads packed as 2 f32x2 accumulator pairs. Register-staged pipeline.
// =====================================================================
__global__ void __launch_bounds__(224) kernelA(const float* __restrict__ x,
                                               const float* __restrict__ attn_w,
                                               const float* __restrict__ attn_b) {
    __shared__ __align__(16) ull s_w[64][9][2];         // {h0,h1},{h2,h3} packed weights
    __shared__ __align__(16) float s_tile[4][16][60];   // 4 ch x 16 halo rows x 60 (58+pad)
    __shared__ __align__(16) float s_attn[4][784];      // attn for this tile

    const int n = blockIdx.x;
    const int h_base = blockIdx.y * 14;
    const int tid = threadIdx.x;

    // pack attention weights: attn_w is (4, 64, 3, 3)
    for (int i = tid; i < 576; i += 224) {
        int c = i / 9, k = i - c * 9;
        s_w[c][k][0] = pack2(attn_w[c * 9 + k], attn_w[576 + c * 9 + k]);
        s_w[c][k][1] = pack2(attn_w[1152 + c * 9 + k], attn_w[1728 + c * 9 + k]);
    }
    for (int i = tid; i < 4 * 16 * 60; i += 224) ((float*)s_tile)[i] = 0.f;

    // precompute load list (3712 = 4ch x 16r x 58c elements)
    unsigned meta[NLOAD];
#pragma unroll
    for (int k = 0; k < NLOAD; k++) {
        int i = tid + 224 * k;
        unsigned m = 58u;  // dump cell (pad col, never read by compute)
        if (i < 3712) {
            int cc = i / 928;
            int rem = i - cc * 928;
            int r = rem / 58, col = rem - r * 58;
            unsigned so = cc * 960 + r * 60 + col;
            int gh = h_base - 1 + r, gw = col - 1;
            if ((unsigned)gh < 56u && (unsigned)gw < 56u)
                m = so | ((unsigned)(cc * 3136 + gh * 56 + gw) << 12) | (1u << 28);
            else
                m = so;
        }
        meta[k] = m;
    }

    const float* xn = x + n * 200704;
    float stage[NLOAD];
#pragma unroll
    for (int k = 0; k < NLOAD; k++) {
        unsigned m = meta[k];
        stage[k] = (m >> 28) ? __ldg(xn + ((m >> 12) & 0x3FFFu)) : 0.f;
    }

    const bool active = tid < 196;
    const int hi = tid / 14, wi = tid - hi * 14;
    const int w0 = 4 * wi;

    ull acc[4][2];
#pragma unroll
    for (int p = 0; p < 4; p++) { acc[p][0] = 0ull; acc[p][1] = 0ull; }

    for (int c0 = 0; c0 < 64; c0 += 4) {
        __syncthreads();
#pragma unroll
        for (int k = 0; k < NLOAD; k++) ((float*)s_tile)[meta[k] & 0xFFFu] = stage[k];
        __syncthreads();
        if (c0 < 60) {
            const float* src = xn + (c0 + 4) * 3136;
#pragma unroll
            for (int k = 0; k < NLOAD; k++) {
                unsigned m = meta[k];
                stage[k] = (m >> 28) ? __ldg(src + ((m >> 12) & 0x3FFFu)) : 0.f;
            }
        }
        if (active) {
#pragma unroll
            for (int cc = 0; cc < 4; cc++) {
#pragma unroll
                for (int r = 0; r < 3; r++) {
                    const float* rp = &s_tile[cc][hi + r][w0];
                    float4 a = *(const float4*)rp;
                    float2 b = *(const float2*)(rp + 4);
                    ull p0 = pack2(a.x, a.x), p1 = pack2(a.y, a.y), p2 = pack2(a.z, a.z);
                    ull p3 = pack2(a.w, a.w), p4 = pack2(b.x, b.x), p5 = pack2(b.y, b.y);
                    ull wl, wh;
                    wl = s_w[c0 + cc][r * 3 + 0][0]; wh = s_w[c0 + cc][r * 3 + 0][1];
                    acc[0][0] = fma2(p0, wl, acc[0][0]); acc[1][0] = fma2(p1, wl, acc[1][0]);
                    acc[2][0] = fma2(p2, wl, acc[2][0]); acc[3][0] = fma2(p3, wl, acc[3][0]);
                    acc[0][1] = fma2(p0, wh, acc[0][1]); acc[1][1] = fma2(p1, wh, acc[1][1]);
                    acc[2][1] = fma2(p2, wh, acc[2][1]); acc[3][1] = fma2(p3, wh, acc[3][1]);
                    wl = s_w[c0 + cc][r * 3 + 1][0]; wh = s_w[c0 + cc][r * 3 + 1][1];
                    acc[0][0] = fma2(p1, wl, acc[0][0]); acc[1][0] = fma2(p2, wl, acc[1][0]);
                    acc[2][0] = fma2(p3, wl, acc[2][0]); acc[3][0] = fma2(p4, wl, acc[3][0]);
                    acc[0][1] = fma2(p1, wh, acc[0][1]); acc[1][1] = fma2(p2, wh, acc[1][1]);
                    acc[2][1] = fma2(p3, wh, acc[2][1]); acc[3][1] = fma2(p4, wh, acc[3][1]);
                    wl = s_w[c0 + cc][r * 3 + 2][0]; wh = s_w[c0 + cc][r * 3 + 2][1];
                    acc[0][0] = fma2(p2, wl, acc[0][0]); acc[1][0] = fma2(p3, wl, acc[1][0]);
                    acc[2][0] = fma2(p4, wl, acc[2][0]); acc[3][0] = fma2(p5, wl, acc[3][0]);
                    acc[0][1] = fma2(p2, wh, acc[0][1]); acc[1][1] = fma2(p3, wh, acc[1][1]);
                    acc[2][1] = fma2(p4, wh, acc[2][1]); acc[3][1] = fma2(p5, wh, acc[3][1]);
                }
            }
        }
    }

    if (active) {
        float b0 = attn_b[0], b1 = attn_b[1], b2 = attn_b[2], b3v = attn_b[3];
#pragma unroll
        for (int p = 0; p < 4; p++) {
            float a0, a1, a2, a3;
            unpack2(acc[p][0], a0, a1);
            unpack2(acc[p][1], a2, a3);
            a0 = fmaxf(a0 + b0, 0.f);
            a1 = fmaxf(a1 + b1, 0.f);
            a2 = fmaxf(a2 + b2, 0.f);
            a3 = fmaxf(a3 + b3v, 0.f);
            int px = hi * 56 + w0 + p;
            s_attn[0][px] = 1.f / (1.f + __expf(-a0));
            s_attn[1][px] = 1.f / (1.f + __expf(-a1));
            s_attn[2][px] = 1.f / (1.f + __expf(-a2));
            s_attn[3][px] = 1.f / (1.f + __expf(-a3));
        }
    }
    __syncthreads();

    // phase 2: x2 = x * attn, BN partial sums (deterministic slots)
    const int warp = tid >> 5, lane = tid & 31;
    const int pidx = n * 4 + blockIdx.y;  // 0..511
    for (int c = warp; c < 64; c += 7) {
        int head = c >> 4;
        const float4* xp = (const float4*)(xn + c * 3136 + h_base * 56);
        float4* x2p = (float4*)(g_x2 + n * 200704 + c * 3136 + h_base * 56);
        const float4* ap = (const float4*)&s_attn[head][0];
        float sum = 0.f, sq = 0.f;
        for (int i = lane; i < 196; i += 32) {
            float4 xv = xp[i], av = ap[i];
            float4 v;
            v.x = xv.x * av.x;
            v.y = xv.y * av.y;
            v.z = xv.z * av.z;
            v.w = xv.w * av.w;
            x2p[i] = v;
            sum += (v.x + v.y) + (v.z + v.w);
            sq += (v.x * v.x + v.y * v.y) + (v.z * v.z + v.w * v.w);
        }
#pragma unroll
        for (int o = 16; o; o >>= 1) {
            sum += __shfl_down_sync(0xffffffffu, sum, o);
            sq += __shfl_down_sync(0xffffffffu, sq, o);
        }
        if (lane == 0) {
            g_psum[c * 512 + pidx] = sum;
            g_psq[c * 512 + pidx] = sq;
        }
    }
}

// =====================================================================
// Kernel B: reduce BN partials -> per-channel scale/bias. grid 64, block 32.
// =====================================================================
__global__ void kernelB(const float* __restrict__ gamma, const float* __restrict__ beta) {
    int c = blockIdx.x, lane = threadIdx.x;
    float s = 0.f, q = 0.f;
    for (int i = lane; i < 512; i += 32) {
        s += g_psum[c * 512 + i];
        q += g_psq[c * 512 + i];
    }
#pragma unroll
    for (int o = 16; o; o >>= 1) {
        s += __shfl_down_sync(0xffffffffu, s, o);
        q += __shfl_down_sync(0xffffffffu, q, o);
    }
    if (lane == 0) {
        const float inv_n = 1.f / 401408.f;  // B*T*H*W
        float mean = s * inv_n;
        float var = q * inv_n - mean * mean;
        float sc = gamma[c] * rsqrtf(var + EPS);
        g_scale[c] = sc;
        g_bias[c] = beta[c] - mean * sc;
    }
}

// =====================================================================
// Kernel C: grouped conv3d (3x3x3, 32ch -> 1 per group) on relu(bn(x2)),
//           tanh -> g_gate. Two output time-steps per block packed as f32x2.
// grid (64 [b*4+tpair], 2 g, 4 htile), block 224; 196 active, 1h x 4w each.
// =====================================================================
__global__ void __launch_bounds__(224) kernelC(const float* __restrict__ w3,
                                               const float* __restrict__ b3) {
    __shared__ __align__(16) ull s_wp[4][32][9];        // [slice_rel][c][tap] = (w_t0, w_t1)
    __shared__ __align__(16) float s_tile[4][16][60];
    __shared__ float s_sc[32], s_bi[32];

    const int bx = blockIdx.x;  // 0..63
    const int b = bx >> 2;
    const int t0 = (bx & 3) * 2;
    const int g = blockIdx.y;
    const int h_base = blockIdx.z * 14;
    const int tid = threadIdx.x;

    // pre-pair weights per slice-relative position:
    // slice ts = t0-1+srel contributes to (t0 with dt=srel, t0+1 with dt=srel-1)
    for (int i = tid; i < 288; i += 224) {
        int c = i / 9, k = i - c * 9;
        float w0v = w3[g * 864 + c * 27 + k];
        float w1v = w3[g * 864 + c * 27 + 9 + k];
        float w2v = w3[g * 864 + c * 27 + 18 + k];
        s_wp[0][c][k] = pack2(w0v, 0.f);
        s_wp[1][c][k] = pack2(w1v, w0v);
        s_wp[2][c][k] = pack2(w2v, w1v);
        s_wp[3][c][k] = pack2(0.f, w2v);
    }
    if (tid < 32) {
        s_sc[tid] = g_scale[g * 32 + tid];
        s_bi[tid] = g_bias[g * 32 + tid];
    }
    for (int i = tid; i < 4 * 16 * 60; i += 224) ((float*)s_tile)[i] = 0.f;

    unsigned meta[NLOAD];
#pragma unroll
    for (int k = 0; k < NLOAD; k++) {
        int i = tid + 224 * k;
        unsigned m = 58u;
        if (i < 3712) {
            int cc = i / 928;
            int rem = i - cc * 928;
            int r = rem / 58, col = rem - r * 58;
            unsigned so = cc * 960 + r * 60 + col;
            int gh = h_base - 1 + r, gw = col - 1;
            if ((unsigned)gh < 56u && (unsigned)gw < 56u)
                m = so | ((unsigned)(cc * 3136 + gh * 56 + gw) << 12) | ((unsigned)cc << 26) |
                    (1u << 28);
            else
                m = so | ((unsigned)cc << 26);
        }
        meta[k] = m;
    }

    const int srel0 = (t0 == 0) ? 1 : 0;
    const int srel1 = (t0 == 6) ? 2 : 3;  // inclusive
    const int nst = (srel1 - srel0 + 1) * 8;

    // prefetch stage 0
    float stage[NLOAD];
    {
        int ts = t0 - 1 + srel0;
        const float* src = g_x2 + ((b * 8 + ts) * 64 + g * 32) * 3136;
#pragma unroll
        for (int k = 0; k < NLOAD; k++) {
            unsigned m = meta[k];
            stage[k] = (m >> 28) ? __ldg(src + ((m >> 12) & 0x3FFFu)) : 0.f;
        }
    }

    const bool active = tid < 196;
    const int hi = tid / 14, wi = tid - hi * 14;
    const int w0c = 4 * wi;

    ull acc[4] = {0ull, 0ull, 0ull, 0ull};

    for (int s = 0; s < nst; s++) {
        const int srel = srel0 + (s >> 3);
        const int c0 = (s & 7) * 4;
        __syncthreads();
#pragma unroll
        for (int k = 0; k < NLOAD; k++) {
            unsigned m = meta[k];
            int cc = (m >> 26) & 3;
            float v = fmaxf(fmaf(stage[k], s_sc[c0 + cc], s_bi[c0 + cc]), 0.f);
            if (!(m >> 28)) v = 0.f;  // spatial zero-pad AFTER bn+relu
            ((float*)s_tile)[m & 0xFFFu] = v;
        }
        __syncthreads();
        if (s + 1 < nst) {
            int srn = srel0 + ((s + 1) >> 3);
            int tsn = t0 - 1 + srn;
            int c0n = ((s + 1) & 7) * 4;
            const float* src = g_x2 + ((b * 8 + tsn) * 64 + g * 32 + c0n) * 3136;
#pragma unroll
            for (int k = 0; k < NLOAD; k++) {
                unsigned m = meta[k];
                stage[k] = (m >> 28) ? __ldg(src + ((m >> 12) & 0x3FFFu)) : 0.f;
            }
        }
        if (active) {
#pragma unroll
            for (int cc = 0; cc < 4; cc++) {
                const ull* wv = s_wp[srel][c0 + cc];
#pragma unroll
                for (int r = 0; r < 3; r++) {
                    const float* rp = &s_tile[cc][hi + r][w0c];
                    float4 a = *(const float4*)rp;
                    float2 bq = *(const float2*)(rp + 4);
                    ull p0 = pack2(a.x, a.x), p1 = pack2(a.y, a.y), p2 = pack2(a.z, a.z);
                    ull p3 = pack2(a.w, a.w), p4 = pack2(bq.x, bq.x), p5 = pack2(bq.y, bq.y);
                    ull w;
                    w = wv[r * 3 + 0];
                    acc[0] = fma2(p0, w, acc[0]); acc[1] = fma2(p1, w, acc[1]);
                    acc[2] = fma2(p2, w, acc[2]); acc[3] = fma2(p3, w, acc[3]);
                    w = wv[r * 3 + 1];
                    acc[0] = fma2(p1, w, acc[0]); acc[1] = fma2(p2, w, acc[1]);
                    acc[2] = fma2(p3, w, acc[2]); acc[3] = fma2(p4, w, acc[3]);
                    w = wv[r * 3 + 2];
                    acc[0] = fma2(p2, w, acc[0]); acc[1] = fma2(p3, w, acc[1]);
                    acc[2] = fma2(p4, w, acc[2]); acc[3] = fma2(p5, w, acc[3]);
                }
            }
        }
    }

    if (active) {
        float cb = b3[g];
        int hw = (h_base + hi) * 56 + w0c;
        float* gp0 = g_gate + ((g * 16 + b) * 8 + t0) * 3136 + hw;
        float* gp1 = gp0 + 3136;
#pragma unroll
        for (int p = 0; p < 4; p++) {
            float o0, o1;
            unpack2(acc[p], o0, o1);
            gp0[p] = tanhf(o0 + cb);
            gp1[p] = tanhf(o1 + cb);
        }
    }
}

// =====================================================================
// Kernel D: gate apply + temporal shift + channel interleave, float4 streaming.
// =====================================================================
__global__ void __launch_bounds__(256) kernelD(float* __restrict__ out) {
    int idx = blockIdx.x * 256 + threadIdx.x;  // 0..802815
    int w4 = idx % 14;
    int tmp = idx / 14;
    int h = tmp % 56;
    tmp /= 56;
    int c_out = tmp & 63;
    int b = tmp >> 6;

    int gsel = c_out >> 5;
    int cc = c_out & 31;
    int c_src = gsel * 32 + (cc & 1) * 16 + (cc >> 1);  // de-interleave

    int hw = h * 56 + w4 * 4;
    const float4* gbase = (const float4*)(g_gate + ((gsel * 16 + b) * 8) * 3136 + hw);
    int xoff0 = (b * 8) * 64 * 3136 + c_src * 3136 + hw;
    int ooff0 = (b * 8) * 64 * 3136 + c_out * 3136 + hw;

    float4 py = make_float4(0.f, 0.f, 0.f, 0.f);
    if (gsel == 0) {
#pragma unroll
        for (int t = 7; t >= 0; --t) {
            float4 xt = *(const float4*)(g_x2 + xoff0 + t * 64 * 3136);
            float4 gt = gbase[t * 784];
            float4 o;
            o.x = py.x + (1.f - gt.x) * xt.x;
            o.y = py.y + (1.f - gt.y) * xt.y;
            o.z = py.z + (1.f - gt.z) * xt.z;
            o.w = py.w + (1.f - gt.w) * xt.w;
            *(float4*)(out + ooff0 + t * 64 * 3136) = o;
            py.x = gt.x * xt.x;
            py.y = gt.y * xt.y;
            py.z = gt.z * xt.z;
            py.w = gt.w * xt.w;
        }
    } else {
#pragma unroll
        for (int t = 0; t < 8; ++t) {
            float4 xt = *(const float4*)(g_x2 + xoff0 + t * 64 * 3136);
            float4 gt = gbase[t * 784];
            float4 o;
            o.x = py.x + (1.f - gt.x) * xt.x;
            o.y = py.y + (1.f - gt.y) * xt.y;
            o.z = py.z + (1.f - gt.z) * xt.z;
            o.w = py.w + (1.f - gt.w) * xt.w;
            *(float4*)(out + ooff0 + t * 64 * 3136) = o;
            py.x = gt.x * xt.x;
            py.y = gt.y * xt.y;
            py.z = gt.z * xt.z;
            py.w = gt.w * xt.w;
        }
    }
}

// =====================================================================
extern "C" void kernel_launch(void* const* d_in, const int* in_sizes, int n_in,
                              void* d_out, int out_size) {
    const float* x = (const float*)d_in[0];
    const float* attn_w = (const float*)d_in[1];
    const float* attn_b = (const float*)d_in[2];
    const float* gamma = (const float*)d_in[3];
    const float* beta = (const float*)d_in[4];
    const float* w3 = (const float*)d_in[5];
    const float* b3 = (const float*)d_in[6];
    float* out = (float*)d_out;

    kernelA<<<dim3(128, 4), 224>>>(x, attn_w, attn_b);
    kernelB<<<64, 32>>>(gamma, beta);
    kernelC<<<dim3(64, 2, 4), 224>>>(w3, b3);
    kernelD<<<3136, 256>>>(out);
}

// round 6
// speedup vs baseline: 1.4618x; 1.0185x over previous
#include <cuda_runtime.h>

#define EPS 1e-5f

typedef unsigned long long ull;

// ---------------- scratch (static device memory; no allocations) ----------------
static __device__ __align__(16) float g_x2[128 * 64 * 3136];       // 102.8 MB: x * attn
static __device__ __align__(16) float g_gate[2 * 16 * 8 * 3136];   // 3.2 MB : tanh(conv3d)
static __device__ float g_psum[64 * 512];                          // BN partial sums
static __device__ float g_psq[64 * 512];                           // BN partial sumsq
static __device__ float g_scale[64];
static __device__ float g_bias[64];

// ---------------- helpers ----------------
__device__ __forceinline__ ull pack2(float a, float b) {
    ull r;
    asm("mov.b64 %0, {%1, %2};" : "=l"(r) : "r"(__float_as_uint(a)), "r"(__float_as_uint(b)));
    return r;
}
__device__ __forceinline__ void unpack2(ull v, float& a, float& b) {
    unsigned int ua, ub;
    asm("mov.b64 {%0, %1}, %2;" : "=r"(ua), "=r"(ub) : "l"(v));
    a = __uint_as_float(ua);
    b = __uint_as_float(ub);
}
__device__ __forceinline__ ull fma2(ull a, ull b, ull c) {
    ull d;
    asm("fma.rn.f32x2 %0, %1, %2, %3;" : "=l"(d) : "l"(a), "l"(b), "l"(c));
    return d;
}
// R2-proven accurate forms. MUFU.TANH / expf-composed tanh both FAILED the 1e-3
// threshold (R3: 2.7e-3, R4: 3.9e-3) — do not substitute.
__device__ __forceinline__ float sigmoid_exact(float x) {
    return 1.f / (1.f + __expf(-x));
}

// meta layout: bits[0:12) smem offset, [12:26) gmem offset, [26:28) cc, [28] valid
#define NLOAD 17  // ceil(3712 / 224)

// =====================================================================
// Kernel A: attn conv2d (4 heads, 3x3, C=64) -> sigmoid(relu(.)),
//           x2 = x * attn, BN partial sums.
// grid (128, 4), block 224. Tile 14h x 56w, thread (of 196) = 1h x 4w,
// heads packed as 2 f32x2 pairs. Double-buffered smem, 1 sync/stage.
// =====================================================================
__global__ void __launch_bounds__(224) kernelA(const float* __restrict__ x,
                                               const float* __restrict__ attn_w,
                                               const float* __restrict__ attn_b) {
    __shared__ __align__(16) ull s_w[64][9][2];
    __shared__ __align__(16) float s_tile[2][4][16][60];
    __shared__ __align__(16) float s_attn[4][784];

    const int n = blockIdx.x;
    const int h_base = blockIdx.y * 14;
    const int tid = threadIdx.x;

    for (int i = tid; i < 576; i += 224) {
        int c = i / 9, k = i - c * 9;
        s_w[c][k][0] = pack2(attn_w[c * 9 + k], attn_w[576 + c * 9 + k]);
        s_w[c][k][1] = pack2(attn_w[1152 + c * 9 + k], attn_w[1728 + c * 9 + k]);
    }
    // NOTE: s_w is first READ only after the stage-0 __syncthreads() below,
    // so no extra barrier is needed here.

    unsigned meta[NLOAD];
#pragma unroll
    for (int k = 0; k < NLOAD; k++) {
        int i = tid + 224 * k;
        unsigned m = 58u;  // dump cell (never read by compute; written with 0)
        if (i < 3712) {
            int cc = i / 928;
            int rem = i - cc * 928;
            int r = rem / 58, col = rem - r * 58;
            unsigned so = cc * 960 + r * 60 + col;
            int gh = h_base - 1 + r, gw = col - 1;
            if ((unsigned)gh < 56u && (unsigned)gw < 56u)
                m = so | ((unsigned)(cc * 3136 + gh * 56 + gw) << 12) | (1u << 28);
            else
                m = so;
        }
        meta[k] = m;
    }

    const float* xn = x + n * 200704;
    float stage[NLOAD];
#pragma unroll
    for (int k = 0; k < NLOAD; k++) {
        unsigned m = meta[k];
        stage[k] = (m >> 28) ? __ldg(xn + ((m >> 12) & 0x3FFFu)) : 0.f;
    }

    const bool active = tid < 196;
    const int hi = tid / 14, wi = tid - hi * 14;
    const int w0 = 4 * wi;

    ull acc[4][2];
#pragma unroll
    for (int p = 0; p < 4; p++) { acc[p][0] = 0ull; acc[p][1] = 0ull; }

    for (int s = 0; s < 16; s++) {
        const int c0 = s * 4;
        float* tb = &s_tile[s & 1][0][0][0];
#pragma unroll
        for (int k = 0; k < NLOAD; k++) tb[meta[k] & 0xFFFu] = stage[k];
        __syncthreads();
        if (s < 15) {
            const float* src = xn + (c0 + 4) * 3136;
#pragma unroll
            for (int k = 0; k < NLOAD; k++) {
                unsigned m = meta[k];
                stage[k] = (m >> 28) ? __ldg(src + ((m >> 12) & 0x3FFFu)) : 0.f;
            }
        }
        if (active) {
            const float(*tile)[16][60] = (const float(*)[16][60])tb;
#pragma unroll
            for (int cc = 0; cc < 4; cc++) {
#pragma unroll
                for (int r = 0; r < 3; r++) {
                    const float* rp = &tile[cc][hi + r][w0];
                    float4 a = *(const float4*)rp;
                    float2 b = *(const float2*)(rp + 4);
                    ull p0 = pack2(a.x, a.x), p1 = pack2(a.y, a.y), p2 = pack2(a.z, a.z);
                    ull p3 = pack2(a.w, a.w), p4 = pack2(b.x, b.x), p5 = pack2(b.y, b.y);
                    ull wl, wh;
                    wl = s_w[c0 + cc][r * 3 + 0][0]; wh = s_w[c0 + cc][r * 3 + 0][1];
                    acc[0][0] = fma2(p0, wl, acc[0][0]); acc[1][0] = fma2(p1, wl, acc[1][0]);
                    acc[2][0] = fma2(p2, wl, acc[2][0]); acc[3][0] = fma2(p3, wl, acc[3][0]);
                    acc[0][1] = fma2(p0, wh, acc[0][1]); acc[1][1] = fma2(p1, wh, acc[1][1]);
                    acc[2][1] = fma2(p2, wh, acc[2][1]); acc[3][1] = fma2(p3, wh, acc[3][1]);
                    wl = s_w[c0 + cc][r * 3 + 1][0]; wh = s_w[c0 + cc][r * 3 + 1][1];
                    acc[0][0] = fma2(p1, wl, acc[0][0]); acc[1][0] = fma2(p2, wl, acc[1][0]);
                    acc[2][0] = fma2(p3, wl, acc[2][0]); acc[3][0] = fma2(p4, wl, acc[3][0]);
                    acc[0][1] = fma2(p1, wh, acc[0][1]); acc[1][1] = fma2(p2, wh, acc[1][1]);
                    acc[2][1] = fma2(p3, wh, acc[2][1]); acc[3][1] = fma2(p4, wh, acc[3][1]);
                    wl = s_w[c0 + cc][r * 3 + 2][0]; wh = s_w[c0 + cc][r * 3 + 2][1];
                    acc[0][0] = fma2(p2, wl, acc[0][0]); acc[1][0] = fma2(p3, wl, acc[1][0]);
                    acc[2][0] = fma2(p4, wl, acc[2][0]); acc[3][0] = fma2(p5, wl, acc[3][0]);
                    acc[0][1] = fma2(p2, wh, acc[0][1]); acc[1][1] = fma2(p3, wh, acc[1][1]);
                    acc[2][1] = fma2(p4, wh, acc[2][1]); acc[3][1] = fma2(p5, wh, acc[3][1]);
                }
            }
        }
    }

    if (active) {
        float b0 = attn_b[0], b1 = attn_b[1], b2 = attn_b[2], b3v = attn_b[3];
#pragma unroll
        for (int p = 0; p < 4; p++) {
            float a0, a1, a2, a3;
            unpack2(acc[p][0], a0, a1);
            unpack2(acc[p][1], a2, a3);
            a0 = fmaxf(a0 + b0, 0.f);
            a1 = fmaxf(a1 + b1, 0.f);
            a2 = fmaxf(a2 + b2, 0.f);
            a3 = fmaxf(a3 + b3v, 0.f);
            int px = hi * 56 + w0 + p;
            s_attn[0][px] = sigmoid_exact(a0);
            s_attn[1][px] = sigmoid_exact(a1);
            s_attn[2][px] = sigmoid_exact(a2);
            s_attn[3][px] = sigmoid_exact(a3);
        }
    }
    __syncthreads();

    // phase 2: x2 = x * attn, BN partial sums (deterministic slots)
    const int warp = tid >> 5, lane = tid & 31;
    const int pidx = n * 4 + blockIdx.y;
    for (int c = warp; c < 64; c += 7) {
        int head = c >> 4;
        const float4* xp = (const float4*)(xn + c * 3136 + h_base * 56);
        float4* x2p = (float4*)(g_x2 + n * 200704 + c * 3136 + h_base * 56);
        const float4* ap = (const float4*)&s_attn[head][0];
        float sum = 0.f, sq = 0.f;
        for (int i = lane; i < 196; i += 32) {
            float4 xv = xp[i], av = ap[i];
            float4 v;
            v.x = xv.x * av.x;
            v.y = xv.y * av.y;
            v.z = xv.z * av.z;
            v.w = xv.w * av.w;
            x2p[i] = v;
            sum += (v.x + v.y) + (v.z + v.w);
            sq += (v.x * v.x + v.y * v.y) + (v.z * v.z + v.w * v.w);
        }
#pragma unroll
        for (int o = 16; o; o >>= 1) {
            sum += __shfl_down_sync(0xffffffffu, sum, o);
            sq += __shfl_down_sync(0xffffffffu, sq, o);
        }
        if (lane == 0) {
            g_psum[c * 512 + pidx] = sum;
            g_psq[c * 512 + pidx] = sq;
        }
    }
}

// =====================================================================
// Kernel B: reduce BN partials -> per-channel scale/bias. grid 64, block 32.
// =====================================================================
__global__ void kernelB(const float* __restrict__ gamma, const float* __restrict__ beta) {
    int c = blockIdx.x, lane = threadIdx.x;
    float s = 0.f, q = 0.f;
    for (int i = lane; i < 512; i += 32) {
        s += g_psum[c * 512 + i];
        q += g_psq[c * 512 + i];
    }
#pragma unroll
    for (int o = 16; o; o >>= 1) {
        s += __shfl_down_sync(0xffffffffu, s, o);
        q += __shfl_down_sync(0xffffffffu, q, o);
    }
    if (lane == 0) {
        const float inv_n = 1.f / 401408.f;
        float mean = s * inv_n;
        float var = q * inv_n - mean * mean;
        float sc = gamma[c] * rsqrtf(var + EPS);
        g_scale[c] = sc;
        g_bias[c] = beta[c] - mean * sc;
    }
}

// ---------------- one t-pair conv contribution (3x3 over 4 channels) ----------------
__device__ __forceinline__ void conv_pair(const float(*tile)[16][60], const ull(*wt)[9],
                                          int hi, int w0, ull* acc) {
#pragma unroll
    for (int cc = 0; cc < 4; cc++) {
        const ull* wv = wt[cc];
#pragma unroll
        for (int r = 0; r < 3; r++) {
            const float* rp = &tile[cc][hi + r][w0];
            float4 a = *(const float4*)rp;
            float2 b = *(const float2*)(rp + 4);
            ull p0 = pack2(a.x, a.x), p1 = pack2(a.y, a.y), p2 = pack2(a.z, a.z);
            ull p3 = pack2(a.w, a.w), p4 = pack2(b.x, b.x), p5 = pack2(b.y, b.y);
            ull w;
            w = wv[r * 3 + 0];
            acc[0] = fma2(p0, w, acc[0]); acc[1] = fma2(p1, w, acc[1]);
            acc[2] = fma2(p2, w, acc[2]); acc[3] = fma2(p3, w, acc[3]);
            w = wv[r * 3 + 1];
            acc[0] = fma2(p1, w, acc[0]); acc[1] = fma2(p2, w, acc[1]);
            acc[2] = fma2(p3, w, acc[2]); acc[3] = fma2(p4, w, acc[3]);
            w = wv[r * 3 + 2];
            acc[0] = fma2(p2, w, acc[0]); acc[1] = fma2(p3, w, acc[1]);
            acc[2] = fma2(p4, w, acc[2]); acc[3] = fma2(p5, w, acc[3]);
        }
    }
}

// =====================================================================
// Kernel C: grouped conv3d (3x3x3, 32ch -> 1 per group) on relu(bn(x2)),
//           tanh -> g_gate. t-QUAD blocks: 4 output t's as 2 f32x2 pairs,
//           5 input slices per block (1.25 loads/output).
// grid (32 [b*2+quad], 2 g, 4 htile), block 224; 196 active, 1h x 4w each.
// =====================================================================
__global__ void __launch_bounds__(224) kernelC(const float* __restrict__ w3,
                                               const float* __restrict__ b3) {
    __shared__ __align__(16) ull s_wp[4][32][9];  // [j][c][tap] = (W(j), W(j-1))
    __shared__ __align__(16) float s_tile[2][4][16][60];
    __shared__ float s_sc[32], s_bi[32];

    const int bx = blockIdx.x;          // 0..31
    const int b = bx >> 1;
    const int t0 = (bx & 1) * 4;        // quad base
    const int g = blockIdx.y;
    const int h_base = blockIdx.z * 14;
    const int tid = threadIdx.x;

    for (int i = tid; i < 288; i += 224) {
        int c = i / 9, k = i - c * 9;
        float w0v = w3[g * 864 + c * 27 + k];
        float w1v = w3[g * 864 + c * 27 + 9 + k];
        float w2v = w3[g * 864 + c * 27 + 18 + k];
        s_wp[0][c][k] = pack2(w0v, 0.f);
        s_wp[1][c][k] = pack2(w1v, w0v);
        s_wp[2][c][k] = pack2(w2v, w1v);
        s_wp[3][c][k] = pack2(0.f, w2v);
    }
    if (tid < 32) {
        s_sc[tid] = g_scale[g * 32 + tid];
        s_bi[tid] = g_bias[g * 32 + tid];
    }
    // CRITICAL: the tile-write phase of stage 0 reads s_sc/s_bi (written by
    // warp 0 only) BEFORE the in-loop barrier. This barrier orders the init
    // against those reads. Its absence was the R3/R4/R5 1.7e-3 error.
    __syncthreads();

    unsigned meta[NLOAD];
#pragma unroll
    for (int k = 0; k < NLOAD; k++) {
        int i = tid + 224 * k;
        unsigned m = 58u;
        if (i < 3712) {
            int cc = i / 928;
            int rem = i - cc * 928;
            int r = rem / 58, col = rem - r * 58;
            unsigned so = cc * 960 + r * 60 + col;
            int gh = h_base - 1 + r, gw = col - 1;
            if ((unsigned)gh < 56u && (unsigned)gw < 56u)
                m = so | ((unsigned)(cc * 3136 + gh * 56 + gw) << 12) | ((unsigned)cc << 26) |
                    (1u << 28);
            else
                m = so | ((unsigned)cc << 26);
        }
        meta[k] = m;
    }

    // slice window: i = ts - (t0-1); valid ts in [0,7]
    const int i_lo = (t0 == 0) ? 1 : 0;   // 5 slices either way
    const int nst = 40;                   // 5 slices x 8 channel-groups

    float stage[NLOAD];
    {
        int ts = t0 - 1 + i_lo;
        const float* src = g_x2 + ((b * 8 + ts) * 64 + g * 32) * 3136;
#pragma unroll
        for (int k = 0; k < NLOAD; k++) {
            unsigned m = meta[k];
            stage[k] = (m >> 28) ? __ldg(src + ((m >> 12) & 0x3FFFu)) : 0.f;
        }
    }

    const bool active = tid < 196;
    const int hi = tid / 14, wi = tid - hi * 14;
    const int w0c = 4 * wi;

    ull accA[4] = {0ull, 0ull, 0ull, 0ull};  // outputs (t0, t0+1)
    ull accB[4] = {0ull, 0ull, 0ull, 0ull};  // outputs (t0+2, t0+3)

    for (int s = 0; s < nst; s++) {
        const int i_sl = i_lo + (s >> 3);
        const int c0 = (s & 7) * 4;
        float* tb = &s_tile[s & 1][0][0][0];
#pragma unroll
        for (int k = 0; k < NLOAD; k++) {
            unsigned m = meta[k];
            int cc = (m >> 26) & 3;
            float v = fmaxf(fmaf(stage[k], s_sc[c0 + cc], s_bi[c0 + cc]), 0.f);
            if (!(m >> 28)) v = 0.f;  // spatial zero-pad AFTER bn+relu
            tb[m & 0xFFFu] = v;
        }
        __syncthreads();
        if (s + 1 < nst) {
            int i_n = i_lo + ((s + 1) >> 3);
            int tsn = t0 - 1 + i_n;
            int c0n = ((s + 1) & 7) * 4;
            const float* src = g_x2 + ((b * 8 + tsn) * 64 + g * 32 + c0n) * 3136;
#pragma unroll
            for (int k = 0; k < NLOAD; k++) {
                unsigned m = meta[k];
                stage[k] = (m >> 28) ? __ldg(src + ((m >> 12) & 0x3FFFu)) : 0.f;
            }
        }
        if (active) {
            const float(*tile)[16][60] = (const float(*)[16][60])tb;
            const int jA = i_sl;       // pair A active when 0 <= jA <= 3
            const int jB = i_sl - 2;   // pair B active when 0 <= jB <= 3
            if (jA <= 3) conv_pair(tile, &s_wp[jA][c0], hi, w0c, accA);
            if (jB >= 0) conv_pair(tile, &s_wp[jB][c0], hi, w0c, accB);
        }
    }

    if (active) {
        float cb = b3[g];
        int hw = (h_base + hi) * 56 + w0c;
        float* gp = g_gate + ((g * 16 + b) * 8 + t0) * 3136 + hw;
#pragma unroll
        for (int p = 0; p < 4; p++) {
            float o0, o1, o2, o3;
            unpack2(accA[p], o0, o1);
            unpack2(accB[p], o2, o3);
            gp[p] = tanhf(o0 + cb);
            gp[3136 + p] = tanhf(o1 + cb);
            gp[2 * 3136 + p] = tanhf(o2 + cb);
            gp[3 * 3136 + p] = tanhf(o3 + cb);
        }
    }
}

// =====================================================================
// Kernel D: gate apply + temporal shift + channel interleave, float4 streaming.
// =====================================================================
__global__ void __launch_bounds__(256) kernelD(float* __restrict__ out) {
    int idx = blockIdx.x * 256 + threadIdx.x;
    int w4 = idx % 14;
    int tmp = idx / 14;
    int h = tmp % 56;
    tmp /= 56;
    int c_out = tmp & 63;
    int b = tmp >> 6;

    int gsel = c_out >> 5;
    int cc = c_out & 31;
    int c_src = gsel * 32 + (cc & 1) * 16 + (cc >> 1);

    int hw = h * 56 + w4 * 4;
    const float4* gbase = (const float4*)(g_gate + ((gsel * 16 + b) * 8) * 3136 + hw);
    int xoff0 = (b * 8) * 64 * 3136 + c_src * 3136 + hw;
    int ooff0 = (b * 8) * 64 * 3136 + c_out * 3136 + hw;

    float4 py = make_float4(0.f, 0.f, 0.f, 0.f);
    if (gsel == 0) {
#pragma unroll
        for (int t = 7; t >= 0; --t) {
            float4 xt = *(const float4*)(g_x2 + xoff0 + t * 64 * 3136);
            float4 gt = gbase[t * 784];
            float4 o;
            o.x = py.x + (1.f - gt.x) * xt.x;
            o.y = py.y + (1.f - gt.y) * xt.y;
            o.z = py.z + (1.f - gt.z) * xt.z;
            o.w = py.w + (1.f - gt.w) * xt.w;
            *(float4*)(out + ooff0 + t * 64 * 3136) = o;
            py.x = gt.x * xt.x;
            py.y = gt.y * xt.y;
            py.z = gt.z * xt.z;
            py.w = gt.w * xt.w;
        }
    } else {
#pragma unroll
        for (int t = 0; t < 8; ++t) {
            float4 xt = *(const float4*)(g_x2 + xoff0 + t * 64 * 3136);
            float4 gt = gbase[t * 784];
            float4 o;
            o.x = py.x + (1.f - gt.x) * xt.x;
            o.y = py.y + (1.f - gt.y) * xt.y;
            o.z = py.z + (1.f - gt.z) * xt.z;
            o.w = py.w + (1.f - gt.w) * xt.w;
            *(float4*)(out + ooff0 + t * 64 * 3136) = o;
            py.x = gt.x * xt.x;
            py.y = gt.y * xt.y;
            py.z = gt.z * xt.z;
            py.w = gt.w * xt.w;
        }
    }
}

// =====================================================================
extern "C" void kernel_launch(void* const* d_in, const int* in_sizes, int n_in,
                              void* d_out, int out_size) {
    const float* x = (const float*)d_in[0];
    const float* attn_w = (const float*)d_in[1];
    const float* attn_b = (const float*)d_in[2];
    const float* gamma = (const float*)d_in[3];
    const float* beta = (const float*)d_in[4];
    const float* w3 = (const float*)d_in[5];
    const float* b3 = (const float*)d_in[6];
    float* out = (float*)d_out;

    kernelA<<<dim3(128, 4), 224>>>(x, attn_w, attn_b);
    kernelB<<<64, 32>>>(gamma, beta);
    kernelC<<<dim3(32, 2, 4), 224>>>(w3, b3);
    kernelD<<<3136, 256>>>(out);
}

// round 7
// speedup vs baseline: 1.5871x; 1.0857x over previous
#include <cuda_runtime.h>

#define EPS 1e-5f

typedef unsigned long long ull;

// ---------------- scratch (static device memory; no allocations) ----------------
static __device__ __align__(16) float g_x2[128 * 64 * 3136];       // 102.8 MB: x * attn
static __device__ __align__(16) float g_gate[2 * 16 * 8 * 3136];   // 3.2 MB : tanh(conv3d)
static __device__ float g_psum[64 * 512];                          // BN partial sums
static __device__ float g_psq[64 * 512];                           // BN partial sumsq
static __device__ float g_scale[64];
static __device__ float g_bias[64];

// ---------------- helpers ----------------
__device__ __forceinline__ ull pack2(float a, float b) {
    ull r;
    asm("mov.b64 %0, {%1, %2};" : "=l"(r) : "r"(__float_as_uint(a)), "r"(__float_as_uint(b)));
    return r;
}
__device__ __forceinline__ void unpack2(ull v, float& a, float& b) {
    unsigned int ua, ub;
    asm("mov.b64 {%0, %1}, %2;" : "=r"(ua), "=r"(ub) : "l"(v));
    a = __uint_as_float(ua);
    b = __uint_as_float(ub);
}
__device__ __forceinline__ ull fma2(ull a, ull b, ull c) {
    ull d;
    asm("fma.rn.f32x2 %0, %1, %2, %3;" : "=l"(d) : "l"(a), "l"(b), "l"(c));
    return d;
}
// R2-proven accurate forms. MUFU.TANH / expf-composed tanh both FAILED the 1e-3
// threshold (R3: 2.7e-3, R4: 3.9e-3) — do not substitute.
__device__ __forceinline__ float sigmoid_exact(float x) {
    return 1.f / (1.f + __expf(-x));
}

// Tile geometry: [4ch][16 rows][68 cols]; interior gw g at col 4+g (g=0..55),
// left halo col 3 / right halo col 60 are ALWAYS zero (full-width tiles).
// Row stride 68 floats = 272B (odd multiple of 16B -> bank-rotating).
#define CH_STRIDE 1088  // 16*68 floats per channel
#define BUF_FLOATS 4352 // 4*1088

// no-op kernels to shift which launch index ncu captures (want kernelA at #6)
__global__ void kNop() {}

// =====================================================================
// Kernel A: attn conv2d (4 heads, 3x3, C=64) -> sigmoid(relu(.)),
//           x2 = x * attn, BN partial sums.
// grid (128, 4), block 224. Tile 14h x 56w, thread (of 196) = 1h x 4w,
// heads packed as 2 f32x2 pairs. Double-buffered smem, 1 sync/stage.
// Loads: per thread-stage 4 x LDG.128 + 4 x STS.128 (one per channel).
// =====================================================================
__global__ void __launch_bounds__(224) kernelA(const float* __restrict__ x,
                                               const float* __restrict__ attn_w,
                                               const float* __restrict__ attn_b) {
    __shared__ __align__(16) ull s_w[64][9][2];
    __shared__ __align__(16) float s_tile[2][4][16][68];
    __shared__ __align__(16) float s_attn[4][784];

    const int n = blockIdx.x;
    const int h_base = blockIdx.y * 14;
    const int tid = threadIdx.x;

    for (int i = tid; i < 576; i += 224) {
        int c = i / 9, k = i - c * 9;
        s_w[c][k][0] = pack2(attn_w[c * 9 + k], attn_w[576 + c * 9 + k]);
        s_w[c][k][1] = pack2(attn_w[1152 + c * 9 + k], attn_w[1728 + c * 9 + k]);
    }
    // pre-zero the always-zero W-halo columns (cols 3 and 60) of both buffers.
    // These cells are never written by stage STS (which covers cols 4..59 only),
    // so there is no write race; first read is after the stage-0 barrier.
    for (int i = tid; i < 2 * 4 * 16; i += 224) {
        int buf = i >> 6, rem = i & 63;
        float* row = &s_tile[buf][rem >> 4][rem & 15][0];
        row[3] = 0.f;
        row[60] = 0.f;
    }

    // per-thread load slot: 224 threads = 16 rows x 14 col-groups; k-th slot = channel k
    const int lr = tid / 14, cg = tid - lr * 14;
    const int gh = h_base - 1 + lr;
    const bool lvalid = (unsigned)gh < 56u;
    const int goff = gh * 56 + cg * 4;
    const int soff = lr * 68 + 4 + cg * 4;

    const float* xn = x + n * 200704;
    const float4 z4 = make_float4(0.f, 0.f, 0.f, 0.f);
    float4 st[4];
#pragma unroll
    for (int cc = 0; cc < 4; cc++)
        st[cc] = lvalid ? *(const float4*)(xn + cc * 3136 + goff) : z4;

    const bool active = tid < 196;
    const int hi = tid / 14, wi = tid - hi * 14;

    ull acc[4][2];
#pragma unroll
    for (int p = 0; p < 4; p++) { acc[p][0] = 0ull; acc[p][1] = 0ull; }

    for (int s = 0; s < 16; s++) {
        const int c0 = s * 4;
        float* tb = &s_tile[s & 1][0][0][0];
#pragma unroll
        for (int cc = 0; cc < 4; cc++) *(float4*)(tb + cc * CH_STRIDE + soff) = st[cc];
        __syncthreads();
        if (s < 15) {
            const float* src = xn + (c0 + 4) * 3136 + goff;
#pragma unroll
            for (int cc = 0; cc < 4; cc++)
                st[cc] = lvalid ? *(const float4*)(src + cc * 3136) : z4;
        }
        if (active) {
#pragma unroll
            for (int cc = 0; cc < 4; cc++) {
#pragma unroll
                for (int r = 0; r < 3; r++) {
                    const float* rp = tb + cc * CH_STRIDE + (hi + r) * 68 + 4 + 4 * wi;
                    float4 q = *(const float4*)rp;
                    float vl = rp[-1], vr = rp[4];
                    // values map to old (a.x,a.y,a.z,a.w,b.x,b.y) = (vl,q.x,q.y,q.z,q.w,vr)
                    ull p0 = pack2(vl, vl), p1 = pack2(q.x, q.x), p2 = pack2(q.y, q.y);
                    ull p3 = pack2(q.z, q.z), p4 = pack2(q.w, q.w), p5 = pack2(vr, vr);
                    ull wl, wh;
                    wl = s_w[c0 + cc][r * 3 + 0][0]; wh = s_w[c0 + cc][r * 3 + 0][1];
                    acc[0][0] = fma2(p0, wl, acc[0][0]); acc[1][0] = fma2(p1, wl, acc[1][0]);
                    acc[2][0] = fma2(p2, wl, acc[2][0]); acc[3][0] = fma2(p3, wl, acc[3][0]);
                    acc[0][1] = fma2(p0, wh, acc[0][1]); acc[1][1] = fma2(p1, wh, acc[1][1]);
                    acc[2][1] = fma2(p2, wh, acc[2][1]); acc[3][1] = fma2(p3, wh, acc[3][1]);
                    wl = s_w[c0 + cc][r * 3 + 1][0]; wh = s_w[c0 + cc][r * 3 + 1][1];
                    acc[0][0] = fma2(p1, wl, acc[0][0]); acc[1][0] = fma2(p2, wl, acc[1][0]);
                    acc[2][0] = fma2(p3, wl, acc[2][0]); acc[3][0] = fma2(p4, wl, acc[3][0]);
                    acc[0][1] = fma2(p1, wh, acc[0][1]); acc[1][1] = fma2(p2, wh, acc[1][1]);
                    acc[2][1] = fma2(p3, wh, acc[2][1]); acc[3][1] = fma2(p4, wh, acc[3][1]);
                    wl = s_w[c0 + cc][r * 3 + 2][0]; wh = s_w[c0 + cc][r * 3 + 2][1];
                    acc[0][0] = fma2(p2, wl, acc[0][0]); acc[1][0] = fma2(p3, wl, acc[1][0]);
                    acc[2][0] = fma2(p4, wl, acc[2][0]); acc[3][0] = fma2(p5, wl, acc[3][0]);
                    acc[0][1] = fma2(p2, wh, acc[0][1]); acc[1][1] = fma2(p3, wh, acc[1][1]);
                    acc[2][1] = fma2(p4, wh, acc[2][1]); acc[3][1] = fma2(p5, wh, acc[3][1]);
                }
            }
        }
    }

    if (active) {
        const int w0 = 4 * wi;
        float b0 = attn_b[0], b1 = attn_b[1], b2 = attn_b[2], b3v = attn_b[3];
#pragma unroll
        for (int p = 0; p < 4; p++) {
            float a0, a1, a2, a3;
            unpack2(acc[p][0], a0, a1);
            unpack2(acc[p][1], a2, a3);
            a0 = fmaxf(a0 + b0, 0.f);
            a1 = fmaxf(a1 + b1, 0.f);
            a2 = fmaxf(a2 + b2, 0.f);
            a3 = fmaxf(a3 + b3v, 0.f);
            int px = hi * 56 + w0 + p;
            s_attn[0][px] = sigmoid_exact(a0);
            s_attn[1][px] = sigmoid_exact(a1);
            s_attn[2][px] = sigmoid_exact(a2);
            s_attn[3][px] = sigmoid_exact(a3);
        }
    }
    __syncthreads();

    // phase 2: x2 = x * attn, BN partial sums (deterministic slots)
    const int warp = tid >> 5, lane = tid & 31;
    const int pidx = n * 4 + blockIdx.y;
    for (int c = warp; c < 64; c += 7) {
        int head = c >> 4;
        const float4* xp = (const float4*)(xn + c * 3136 + h_base * 56);
        float4* x2p = (float4*)(g_x2 + n * 200704 + c * 3136 + h_base * 56);
        const float4* ap = (const float4*)&s_attn[head][0];
        float sum = 0.f, sq = 0.f;
        for (int i = lane; i < 196; i += 32) {
            float4 xv = xp[i], av = ap[i];
            float4 v;
            v.x = xv.x * av.x;
            v.y = xv.y * av.y;
            v.z = xv.z * av.z;
            v.w = xv.w * av.w;
            x2p[i] = v;
            sum += (v.x + v.y) + (v.z + v.w);
            sq += (v.x * v.x + v.y * v.y) + (v.z * v.z + v.w * v.w);
        }
#pragma unroll
        for (int o = 16; o; o >>= 1) {
            sum += __shfl_down_sync(0xffffffffu, sum, o);
            sq += __shfl_down_sync(0xffffffffu, sq, o);
        }
        if (lane == 0) {
            g_psum[c * 512 + pidx] = sum;
            g_psq[c * 512 + pidx] = sq;
        }
    }
}

// =====================================================================
// Kernel B: reduce BN partials -> per-channel scale/bias. grid 64, block 32.
// =====================================================================
__global__ void kernelB(const float* __restrict__ gamma, const float* __restrict__ beta) {
    int c = blockIdx.x, lane = threadIdx.x;
    float s = 0.f, q = 0.f;
    for (int i = lane; i < 512; i += 32) {
        s += g_psum[c * 512 + i];
        q += g_psq[c * 512 + i];
    }
#pragma unroll
    for (int o = 16; o; o >>= 1) {
        s += __shfl_down_sync(0xffffffffu, s, o);
        q += __shfl_down_sync(0xffffffffu, q, o);
    }
    if (lane == 0) {
        const float inv_n = 1.f / 401408.f;
        float mean = s * inv_n;
        float var = q * inv_n - mean * mean;
        float sc = gamma[c] * rsqrtf(var + EPS);
        g_scale[c] = sc;
        g_bias[c] = beta[c] - mean * sc;
    }
}

// ---------------- one t-pair conv contribution (3x3 over 4 channels) ----------------
__device__ __forceinline__ void conv_pair(const float* tb, const ull(*wt)[9],
                                          int hi, int wi, ull* acc) {
#pragma unroll
    for (int cc = 0; cc < 4; cc++) {
        const ull* wv = wt[cc];
#pragma unroll
        for (int r = 0; r < 3; r++) {
            const float* rp = tb + cc * CH_STRIDE + (hi + r) * 68 + 4 + 4 * wi;
            float4 q = *(const float4*)rp;
            float vl = rp[-1], vr = rp[4];
            ull p0 = pack2(vl, vl), p1 = pack2(q.x, q.x), p2 = pack2(q.y, q.y);
            ull p3 = pack2(q.z, q.z), p4 = pack2(q.w, q.w), p5 = pack2(vr, vr);
            ull w;
            w = wv[r * 3 + 0];
            acc[0] = fma2(p0, w, acc[0]); acc[1] = fma2(p1, w, acc[1]);
            acc[2] = fma2(p2, w, acc[2]); acc[3] = fma2(p3, w, acc[3]);
            w = wv[r * 3 + 1];
            acc[0] = fma2(p1, w, acc[0]); acc[1] = fma2(p2, w, acc[1]);
            acc[2] = fma2(p3, w, acc[2]); acc[3] = fma2(p4, w, acc[3]);
            w = wv[r * 3 + 2];
            acc[0] = fma2(p2, w, acc[0]); acc[1] = fma2(p3, w, acc[1]);
            acc[2] = fma2(p4, w, acc[2]); acc[3] = fma2(p5, w, acc[3]);
        }
    }
}

// =====================================================================
// Kernel C: grouped conv3d (3x3x3, 32ch -> 1 per group) on relu(bn(x2)),
//           tanh -> g_gate. t-QUAD blocks: 4 output t's as 2 f32x2 pairs,
//           5 input slices per block (1.25 loads/output).
// grid (32 [b*2+quad], 2 g, 4 htile), block 224; 196 active, 1h x 4w each.
// =====================================================================
__global__ void __launch_bounds__(224) kernelC(const float* __restrict__ w3,
                                               const float* __restrict__ b3) {
    __shared__ __align__(16) ull s_wp[4][32][9];  // [j][c][tap] = (W(j), W(j-1))
    __shared__ __align__(16) float s_tile[2][4][16][68];
    __shared__ float s_sc[32], s_bi[32];

    const int bx = blockIdx.x;          // 0..31
    const int b = bx >> 1;
    const int t0 = (bx & 1) * 4;        // quad base
    const int g = blockIdx.y;
    const int h_base = blockIdx.z * 14;
    const int tid = threadIdx.x;

    for (int i = tid; i < 288; i += 224) {
        int c = i / 9, k = i - c * 9;
        float w0v = w3[g * 864 + c * 27 + k];
        float w1v = w3[g * 864 + c * 27 + 9 + k];
        float w2v = w3[g * 864 + c * 27 + 18 + k];
        s_wp[0][c][k] = pack2(w0v, 0.f);
        s_wp[1][c][k] = pack2(w1v, w0v);
        s_wp[2][c][k] = pack2(w2v, w1v);
        s_wp[3][c][k] = pack2(0.f, w2v);
    }
    if (tid < 32) {
        s_sc[tid] = g_scale[g * 32 + tid];
        s_bi[tid] = g_bias[g * 32 + tid];
    }
    // pre-zero always-zero halo columns of both buffers (disjoint from STS cells)
    for (int i = tid; i < 2 * 4 * 16; i += 224) {
        int buf = i >> 6, rem = i & 63;
        float* row = &s_tile[buf][rem >> 4][rem & 15][0];
        row[3] = 0.f;
        row[60] = 0.f;
    }
    // CRITICAL: the stage-0 tile-write reads s_sc/s_bi (written by warp 0 only)
    // BEFORE the in-loop barrier. This barrier orders the init against those
    // reads (its absence was the R3-R5 1.7e-3 error). It also covers the
    // halo pre-zero vs. first compute read.
    __syncthreads();

    // per-thread load slot
    const int lr = tid / 14, cg = tid - lr * 14;
    const int gh = h_base - 1 + lr;
    const bool lvalid = (unsigned)gh < 56u;
    const int goff = gh * 56 + cg * 4;
    const int soff = lr * 68 + 4 + cg * 4;

    // slice window: i = ts - (t0-1); valid ts in [0,7]
    const int i_lo = (t0 == 0) ? 1 : 0;   // 5 slices either way
    const int nst = 40;                   // 5 slices x 8 channel-groups

    const float4 z4 = make_float4(0.f, 0.f, 0.f, 0.f);
    float4 st[4];
    {
        int ts = t0 - 1 + i_lo;
        const float* src = g_x2 + ((b * 8 + ts) * 64 + g * 32) * 3136 + goff;
#pragma unroll
        for (int cc = 0; cc < 4; cc++)
            st[cc] = lvalid ? *(const float4*)(src + cc * 3136) : z4;
    }

    const bool active = tid < 196;
    const int hi = tid / 14, wi = tid - hi * 14;

    ull accA[4] = {0ull, 0ull, 0ull, 0ull};  // outputs (t0, t0+1)
    ull accB[4] = {0ull, 0ull, 0ull, 0ull};  // outputs (t0+2, t0+3)

    for (int s = 0; s < nst; s++) {
        const int i_sl = i_lo + (s >> 3);
        const int c0 = (s & 7) * 4;
        float* tb = &s_tile[s & 1][0][0][0];
#pragma unroll
        for (int cc = 0; cc < 4; cc++) {
            float sc = s_sc[c0 + cc], bi = s_bi[c0 + cc];
            float4 v;
            if (lvalid) {
                v.x = fmaxf(fmaf(st[cc].x, sc, bi), 0.f);
                v.y = fmaxf(fmaf(st[cc].y, sc, bi), 0.f);
                v.z = fmaxf(fmaf(st[cc].z, sc, bi), 0.f);
                v.w = fmaxf(fmaf(st[cc].w, sc, bi), 0.f);
            } else {
                v = z4;  // spatial zero-pad AFTER bn+relu
            }
            *(float4*)(tb + cc * CH_STRIDE + soff) = v;
        }
        __syncthreads();
        if (s + 1 < nst) {
            int i_n = i_lo + ((s + 1) >> 3);
            int tsn = t0 - 1 + i_n;
            int c0n = ((s + 1) & 7) * 4;
            const float* src = g_x2 + ((b * 8 + tsn) * 64 + g * 32 + c0n) * 3136 + goff;
#pragma unroll
            for (int cc = 0; cc < 4; cc++)
                st[cc] = lvalid ? *(const float4*)(src + cc * 3136) : z4;
        }
        if (active) {
            const int jA = i_sl;       // pair A active when 0 <= jA <= 3
            const int jB = i_sl - 2;   // pair B active when 0 <= jB <= 3
            if (jA <= 3) conv_pair(tb, &s_wp[jA][c0], hi, wi, accA);
            if (jB >= 0) conv_pair(tb, &s_wp[jB][c0], hi, wi, accB);
        }
    }

    if (active) {
        float cb = b3[g];
        int hw = (h_base + hi) * 56 + 4 * wi;
        float* gp = g_gate + ((g * 16 + b) * 8 + t0) * 3136 + hw;
#pragma unroll
        for (int p = 0; p < 4; p++) {
            float o0, o1, o2, o3;
            unpack2(accA[p], o0, o1);
            unpack2(accB[p], o2, o3);
            gp[p] = tanhf(o0 + cb);
            gp[3136 + p] = tanhf(o1 + cb);
            gp[2 * 3136 + p] = tanhf(o2 + cb);
            gp[3 * 3136 + p] = tanhf(o3 + cb);
        }
    }
}

// =====================================================================
// Kernel D: gate apply + temporal shift + channel interleave, float4 streaming.
// =====================================================================
__global__ void __launch_bounds__(256) kernelD(float* __restrict__ out) {
    int idx = blockIdx.x * 256 + threadIdx.x;
    int w4 = idx % 14;
    int tmp = idx / 14;
    int h = tmp % 56;
    tmp /= 56;
    int c_out = tmp & 63;
    int b = tmp >> 6;

    int gsel = c_out >> 5;
    int cc = c_out & 31;
    int c_src = gsel * 32 + (cc & 1) * 16 + (cc >> 1);

    int hw = h * 56 + w4 * 4;
    const float4* gbase = (const float4*)(g_gate + ((gsel * 16 + b) * 8) * 3136 + hw);
    int xoff0 = (b * 8) * 64 * 3136 + c_src * 3136 + hw;
    int ooff0 = (b * 8) * 64 * 3136 + c_out * 3136 + hw;

    float4 py = make_float4(0.f, 0.f, 0.f, 0.f);
    if (gsel == 0) {
#pragma unroll
        for (int t = 7; t >= 0; --t) {
            float4 xt = *(const float4*)(g_x2 + xoff0 + t * 64 * 3136);
            float4 gt = gbase[t * 784];
            float4 o;
            o.x = py.x + (1.f - gt.x) * xt.x;
            o.y = py.y + (1.f - gt.y) * xt.y;
            o.z = py.z + (1.f - gt.z) * xt.z;
            o.w = py.w + (1.f - gt.w) * xt.w;
            *(float4*)(out + ooff0 + t * 64 * 3136) = o;
            py.x = gt.x * xt.x;
            py.y = gt.y * xt.y;
            py.z = gt.z * xt.z;
            py.w = gt.w * xt.w;
        }
    } else {
#pragma unroll
        for (int t = 0; t < 8; ++t) {
            float4 xt = *(const float4*)(g_x2 + xoff0 + t * 64 * 3136);
            float4 gt = gbase[t * 784];
            float4 o;
            o.x = py.x + (1.f - gt.x) * xt.x;
            o.y = py.y + (1.f - gt.y) * xt.y;
            o.z = py.z + (1.f - gt.z) * xt.z;
            o.w = py.w + (1.f - gt.w) * xt.w;
            *(float4*)(out + ooff0 + t * 64 * 3136) = o;
            py.x = gt.x * xt.x;
            py.y = gt.y * xt.y;
            py.z = gt.z * xt.z;
            py.w = gt.w * xt.w;
        }
    }
}

// =====================================================================
extern "C" void kernel_launch(void* const* d_in, const int* in_sizes, int n_in,
                              void* d_out, int out_size) {
    const float* x = (const float*)d_in[0];
    const float* attn_w = (const float*)d_in[1];
    const float* attn_b = (const float*)d_in[2];
    const float* gamma = (const float*)d_in[3];
    const float* beta = (const float*)d_in[4];
    const float* w3 = (const float*)d_in[5];
    const float* b3 = (const float*)d_in[6];
    float* out = (float*)d_out;

    // 3 no-op launches: shifts kernelA into the launch slot ncu captures
    // (-s 5 -c 1 previously always landed on kernelD = slot 6 with 2 harness
    // pre-launches). Costs ~3us; gives the first real profile of kernelA.
    kNop<<<1, 32>>>();
    kNop<<<1, 32>>>();
    kNop<<<1, 32>>>();
    kernelA<<<dim3(128, 4), 224>>>(x, attn_w, attn_b);
    kernelB<<<64, 32>>>(gamma, beta);
    kernelC<<<dim3(32, 2, 4), 224>>>(w3, b3);
    kernelD<<<3136, 256>>>(out);
}